// round 15
// baseline (speedup 1.0000x reference)
#include <cuda_runtime.h>
#include <cuda_bf16.h>
#include <cuda_fp16.h>
#include <math.h>
#include <stdint.h>

#define N_NODES 10000
#define N_EDGES 640000
#define NHID    128
#define EHID    128
#define CSIZE   128

// ---------------- scratch (device globals; no allocation) ----------------
__device__ float g_h_v[N_NODES * NHID];
__device__ __half g_h_v16[N_NODES * NHID];
__device__ __half g_nf16[N_NODES * 64];
__device__ float g_hvdot[N_NODES];
__device__ __half g_h_e16[(size_t)N_EDGES * EHID];  // CSR-ordered rows, fp16 (164MB)
__device__ float g_logit[N_EDGES];                  // CSR-ordered
__device__ __half g_A16[N_NODES * EHID];
__device__ __half g_cv16[N_NODES * CSIZE];
__device__ float g_gi[N_NODES * 3 * NHID];          // [gr | gz | gin] flat, stride 128
__device__ float g_gh[N_NODES * NHID];              // ghn
__device__ int   g_cnt[N_NODES];
__device__ int   g_off[N_NODES + 1];
__device__ int   g_cur[N_NODES];
// fragment images: [ng(2)][k8(8)][q(4)][lane(32)] uint4 each (2048 entries / 128x128 matrix)
__device__ uint4 g_BfragE[2048];        // W_edge^T
__device__ uint4 g_WihFrag[3 * 2048];   // W_ih rows (B[n][k] = Wih[n][k])
__device__ uint4 g_WhhFrag[3 * 2048];
__device__ uint4 g_WmsgFrag[2048];      // W_msg^T

#define A_STRIDE 136   // halves; 272 bytes

__device__ __forceinline__ float leaky01(float v) { return v > 0.f ? v : 0.01f * v; }

__device__ __forceinline__ uint32_t smem_u32(const void* p) {
    uint32_t a;
    asm("{ .reg .u64 t; cvta.to.shared.u64 t, %1; cvt.u32.u64 %0, t; }" : "=r"(a) : "l"(p));
    return a;
}
__device__ __forceinline__ void ldsm_x4(uint32_t* r, uint32_t addr) {
    asm volatile("ldmatrix.sync.aligned.m8n8.x4.shared.b16 {%0,%1,%2,%3}, [%4];"
        : "=r"(r[0]), "=r"(r[1]), "=r"(r[2]), "=r"(r[3]) : "r"(addr));
}
__device__ __forceinline__ void mma_f16(float* c, const uint32_t* a, const uint32_t* b) {
    asm volatile("mma.sync.aligned.m16n8k16.row.col.f32.f16.f16.f32 "
        "{%0,%1,%2,%3}, {%4,%5,%6,%7}, {%8,%9}, {%0,%1,%2,%3};"
        : "+f"(c[0]), "+f"(c[1]), "+f"(c[2]), "+f"(c[3])
        : "r"(a[0]), "r"(a[1]), "r"(a[2]), "r"(a[3]), "r"(b[0]), "r"(b[1]));
}

// fragment builders for mma m16n8k16 .col B fragments
__device__ __forceinline__ uint4 frag_colmajor(const float* M, int f) {  // B[n][k] = M[k*128+n]
    int lane = f & 31, q = (f >> 5) & 3, k8 = (f >> 7) & 7, ng = f >> 10;
    int n1 = ng * 64 + q * 16 + (lane >> 2), n2 = n1 + 8;
    int k0 = k8 * 16 + 2 * (lane & 3);
    uint4 v; __half2 h;
    h = __floats2half2_rn(M[k0 * 128 + n1], M[(k0 + 1) * 128 + n1]); v.x = *(uint32_t*)&h;
    h = __floats2half2_rn(M[(k0 + 8) * 128 + n1], M[(k0 + 9) * 128 + n1]); v.y = *(uint32_t*)&h;
    h = __floats2half2_rn(M[k0 * 128 + n2], M[(k0 + 1) * 128 + n2]); v.z = *(uint32_t*)&h;
    h = __floats2half2_rn(M[(k0 + 8) * 128 + n2], M[(k0 + 9) * 128 + n2]); v.w = *(uint32_t*)&h;
    return v;
}
__device__ __forceinline__ uint4 frag_rowmajor(const float* M, int f, int nbase) { // B[n][k] = M[(nbase+n)*128+k]
    int lane = f & 31, q = (f >> 5) & 3, k8 = (f >> 7) & 7, ng = f >> 10;
    int n1 = nbase + ng * 64 + q * 16 + (lane >> 2), n2 = n1 + 8;
    int k0 = k8 * 16 + 2 * (lane & 3);
    uint4 v; __half2 h;
    h = __floats2half2_rn(M[n1 * 128 + k0], M[n1 * 128 + k0 + 1]); v.x = *(uint32_t*)&h;
    h = __floats2half2_rn(M[n1 * 128 + k0 + 8], M[n1 * 128 + k0 + 9]); v.y = *(uint32_t*)&h;
    h = __floats2half2_rn(M[n2 * 128 + k0], M[n2 * 128 + k0 + 1]); v.z = *(uint32_t*)&h;
    h = __floats2half2_rn(M[n2 * 128 + k0 + 8], M[n2 * 128 + k0 + 9]); v.w = *(uint32_t*)&h;
    return v;
}

// ---------------- launch #1: histogram + nf16 + all fragment-image prep ----------------
__global__ void hist_prep_kernel(const int* __restrict__ dst,
                                 const float* __restrict__ nf,
                                 const float* __restrict__ We,
                                 const float* __restrict__ Wih,
                                 const float* __restrict__ Whh,
                                 const float* __restrict__ Wmsg)
{
    int e = blockIdx.x * blockDim.x + threadIdx.x;
    if (e < N_EDGES) atomicAdd(&g_cnt[dst[e]], 1);
    if (e < N_NODES * 32) {
        float2 f = *(const float2*)&nf[e * 2];
        *(__half2*)&g_nf16[e * 2] = __floats2half2_rn(f.x, f.y);
    }
    if (e < 2048) {
        g_BfragE[e] = frag_colmajor(We, e);
    } else if (e < 2048 + 3 * 2048) {
        int idx = e - 2048;
        g_WihFrag[idx] = frag_rowmajor(Wih, idx & 2047, (idx >> 11) * 128);
    } else if (e < 2048 + 6 * 2048) {
        int idx = e - 2048 - 3 * 2048;
        g_WhhFrag[idx] = frag_rowmajor(Whh, idx & 2047, (idx >> 11) * 128);
    } else if (e < 2048 + 7 * 2048) {
        int idx = e - 2048 - 6 * 2048;
        g_WmsgFrag[idx] = frag_colmajor(Wmsg, idx);
    }
}

// ---------------- launch #2: exclusive scan (warp-shuffle) ----------------
__global__ void scan_kernel() {
    __shared__ int warpsum[32];
    __shared__ int s_carry;
    int t = threadIdx.x, lane = t & 31, w = t >> 5;
    if (t == 0) s_carry = 0;
    __syncthreads();
    for (int base = 0; base < N_NODES; base += 1024) {
        int i = base + t;
        int v = (i < N_NODES) ? g_cnt[i] : 0;
        int x = v;
#pragma unroll
        for (int d = 1; d < 32; d <<= 1) {
            int y = __shfl_up_sync(0xffffffffu, x, d);
            if (lane >= d) x += y;
        }
        if (lane == 31) warpsum[w] = x;
        __syncthreads();
        if (w == 0) {
            int s = warpsum[lane];
#pragma unroll
            for (int d = 1; d < 32; d <<= 1) {
                int y = __shfl_up_sync(0xffffffffu, s, d);
                if (lane >= d) s += y;
            }
            warpsum[lane] = s;
        }
        __syncthreads();
        int incl = x + (w ? warpsum[w - 1] : 0) + s_carry;
        if (i < N_NODES) { g_off[i] = incl - v; g_cur[i] = incl - v; }
        __syncthreads();
        if (t == 1023) s_carry = incl;
        __syncthreads();
    }
    if (t == 0) g_off[N_NODES] = s_carry;
}

// ---------------- launch #3: node embed GEMM (K=64, leaky) + fused hvdot + fp16 copy ----------------
__global__ __launch_bounds__(256) void node_embed_kernel(
    const float* __restrict__ nf, const float* __restrict__ Wn,
    const float* __restrict__ bn, const float* __restrict__ Wl)
{
    extern __shared__ float sm[];
    float* sW = sm;            // 64*128
    float* sX = sm + 8192;     // 64*64
    float* sB = sm + 12288;    // 128
    float* sWL = sm + 12416;   // 128
    int t = threadIdx.x;
    int r0g = blockIdx.x * 64;
    for (int i = t; i < 64 * 128; i += 256) {
        int k = i >> 7, c = i & 127;
        sW[i] = Wn[k * 128 + c];
    }
    for (int i = t; i < 64 * 64; i += 256) {
        int r = i >> 6, k = i & 63;
        int gr = r0g + r;
        sX[i] = (gr < N_NODES) ? nf[gr * 64 + k] : 0.f;
    }
    if (t < 128) { sB[t] = bn[t]; sWL[t] = Wl[t]; }
    __syncthreads();
    int cx = t & 31, cy = t >> 5;
    int r0 = cy * 8, c0 = cx * 4;
    float acc[8][4] = {};
#pragma unroll 4
    for (int k = 0; k < 64; k++) {
        float4 w = *(const float4*)&sW[k * 128 + c0];
#pragma unroll
        for (int r = 0; r < 8; r++) {
            float x = sX[(r0 + r) * 64 + k];
            acc[r][0] += x * w.x; acc[r][1] += x * w.y;
            acc[r][2] += x * w.z; acc[r][3] += x * w.w;
        }
    }
    float wl0 = sWL[c0], wl1 = sWL[c0 + 1], wl2 = sWL[c0 + 2], wl3 = sWL[c0 + 3];
#pragma unroll
    for (int r = 0; r < 8; r++) {
        int gr = r0g + r0 + r;
        if (gr >= N_NODES) break;
        float v0 = leaky01(acc[r][0] + sB[c0]);
        float v1 = leaky01(acc[r][1] + sB[c0 + 1]);
        float v2 = leaky01(acc[r][2] + sB[c0 + 2]);
        float v3 = leaky01(acc[r][3] + sB[c0 + 3]);
        *(float4*)&g_h_v[(size_t)gr * 128 + c0] = make_float4(v0, v1, v2, v3);
        __half2 p01 = __floats2half2_rn(v0, v1);
        __half2 p23 = __floats2half2_rn(v2, v3);
        *(uint2*)&g_h_v16[(size_t)gr * 128 + c0] = make_uint2(*(uint32_t*)&p01, *(uint32_t*)&p23);
        float p = v0 * wl0 + v1 * wl1 + v2 * wl2 + v3 * wl3;
        for (int o = 16; o; o >>= 1) p += __shfl_xor_sync(0xffffffffu, p, o);
        if (cx == 0) g_hvdot[gr] = p;
    }
}

// ============ launch #4: edge GEMM on HMMA, warp tile M=64 x N=32 (B read once/CTA) ============
#define SM_SRC   0
#define SM_PERM  256
#define SM_BIAS  512
#define SM_WL    1024
#define SM_LOG   1536     // 256 floats (64 rows x 4 slices)
#define SM_A     2560
#define SM_EDGE_TOTAL (SM_A + 64 * 272)   // 19968 bytes -> 4 CTAs/SM

__global__ __launch_bounds__(128, 4)
void edge_mma_kernel(const __half* __restrict__ nf16, const float* __restrict__ ef,
                     const int* __restrict__ src, const int* __restrict__ dst,
                     const float* __restrict__ b_edge,
                     const float* __restrict__ W_logit, const float* __restrict__ b_logit,
                     float* __restrict__ outEF)
{
    extern __shared__ __align__(16) char smem[];
    uint32_t sb = smem_u32(smem);
    int t = threadIdx.x, lane = t & 31, wid = t >> 5;
    int e0 = blockIdx.x * 64;
    int* sSrc = (int*)(smem + SM_SRC);
    int* sPerm = (int*)(smem + SM_PERM);
    float* sBias = (float*)(smem + SM_BIAS);
    float* sWL = (float*)(smem + SM_WL);
    float* sLog = (float*)(smem + SM_LOG);

    if (t < 64) {
        sSrc[t] = src[e0 + t];
        sPerm[t] = atomicAdd(&g_cur[dst[e0 + t]], 1);
    }
    sBias[t] = b_edge[t];
    sWL[t] = W_logit[128 + t];
    __syncthreads();

    // ef: single read; passthrough copy + fp16 into A tile (concat cols 64..127)
    {
        const float4* efs = (const float4*)(ef + (size_t)e0 * 64);
        float4* efd = outEF ? (float4*)(outEF + (size_t)e0 * 64) : nullptr;
#pragma unroll
        for (int it = 0; it < 8; it++) {
            int i = t + it * 128;
            float4 v = efs[i];
            if (efd) efd[i] = v;
            int row = i >> 4, j = i & 15;
            __half2 h01 = __floats2half2_rn(v.x, v.y);
            __half2 h23 = __floats2half2_rn(v.z, v.w);
            *(uint2*)(smem + SM_A + row * 272 + 128 + j * 8)
                = make_uint2(*(uint32_t*)&h01, *(uint32_t*)&h23);
        }
    }
    // nf gather: fp16 rows straight into A tile (concat cols 0..63)
    {
        int r = t >> 1, hf = t & 1;
        const uint4* xp = (const uint4*)(nf16 + (size_t)sSrc[r] * 64 + hf * 32);
        uint4* xd = (uint4*)(smem + SM_A + r * 272 + hf * 64);
#pragma unroll
        for (int j = 0; j < 4; j++) xd[j] = xp[j];
    }
    __syncthreads();

    // warp tile: 4 warps, each M=64 (all rows) x N=32 (slice s = wid)
    int s = wid;
    int n0 = s * 32;
    float acc[4][4][4];
#pragma unroll
    for (int i = 0; i < 4; i++)
#pragma unroll
        for (int j = 0; j < 4; j++)
#pragma unroll
            for (int c = 0; c < 4; c++) acc[i][j][c] = 0.f;

    uint32_t aOffL = ((lane & 15) * A_STRIDE + (lane >> 4) * 8) * 2;
    uint32_t Ab = sb + SM_A;
    const uint4* bf = g_BfragE + (s >> 1) * 1024 + lane;
    int qb = (s & 1) * 2;

#pragma unroll
    for (int k8 = 0; k8 < 8; k8++) {
        uint32_t kb = k8 * 32;
        uint4 b0 = bf[k8 * 128 + (qb + 0) * 32];
        uint4 b1 = bf[k8 * 128 + (qb + 1) * 32];
        uint32_t a[4][4];
#pragma unroll
        for (int ms = 0; ms < 4; ms++)
            ldsm_x4(a[ms], Ab + aOffL + (uint32_t)(ms * 16) * 272 + kb);
        const uint32_t* p0 = (const uint32_t*)&b0;
        const uint32_t* p1 = (const uint32_t*)&b1;
#pragma unroll
        for (int ms = 0; ms < 4; ms++) {
            mma_f16(acc[ms][0], a[ms], p0);
            mma_f16(acc[ms][1], a[ms], p0 + 2);
            mma_f16(acc[ms][2], a[ms], p1);
            mma_f16(acc[ms][3], a[ms], p1 + 2);
        }
    }
    __syncthreads();   // A tile reads done -> safe to reuse as h_e staging

    // epilogue: bias + leaky -> smem staging (272B-stride rows) + partial logit
#pragma unroll
    for (int ms = 0; ms < 4; ms++) {
        int r1 = ms * 16 + (lane >> 2);
        int r2 = r1 + 8;
        float lg1 = 0.f, lg2 = 0.f;
#pragma unroll
        for (int ns = 0; ns < 4; ns++) {
            int col = n0 + ns * 8 + (lane & 3) * 2;
            float v0 = leaky01(acc[ms][ns][0] + sBias[col]);
            float v1 = leaky01(acc[ms][ns][1] + sBias[col + 1]);
            float v2 = leaky01(acc[ms][ns][2] + sBias[col]);
            float v3 = leaky01(acc[ms][ns][3] + sBias[col + 1]);
            lg1 += v0 * sWL[col] + v1 * sWL[col + 1];
            lg2 += v2 * sWL[col] + v3 * sWL[col + 1];
            *(__half2*)(smem + SM_A + r1 * 272 + col * 2) = __floats2half2_rn(v0, v1);
            *(__half2*)(smem + SM_A + r2 * 272 + col * 2) = __floats2half2_rn(v2, v3);
        }
        lg1 += __shfl_xor_sync(0xffffffffu, lg1, 1);
        lg1 += __shfl_xor_sync(0xffffffffu, lg1, 2);
        lg2 += __shfl_xor_sync(0xffffffffu, lg2, 1);
        lg2 += __shfl_xor_sync(0xffffffffu, lg2, 2);
        if ((lane & 3) == 0) {
            sLog[r1 * 4 + s] = lg1;
            sLog[r2 * 4 + s] = lg2;
        }
    }
    __syncthreads();

    // coalesced h_e writeout: 2 threads/row, 128B each
    {
        int r = t >> 1, hf = t & 1;
        const uint4* sp = (const uint4*)(smem + SM_A + r * 272 + hf * 128);
        uint4* dp = (uint4*)(g_h_e16 + (size_t)sPerm[r] * 128 + hf * 64);
#pragma unroll
        for (int j = 0; j < 8; j++) dp[j] = sp[j];
    }
    if (t < 64) {
        float sum = sLog[t * 4] + sLog[t * 4 + 1] + sLog[t * 4 + 2] + sLog[t * 4 + 3]
                  + g_hvdot[sSrc[t]] + b_logit[0];
        g_logit[sPerm[t]] = leaky01(sum);
    }
}

// ---------------- launch #5: per-node softmax + weighted sum -> A (fp16), 8x unrolled ----------------
__global__ void aggregate_kernel() {
    int v = (blockIdx.x * blockDim.x + threadIdx.x) >> 5;
    int lane = threadIdx.x & 31;
    if (v >= N_NODES) return;
    int s = g_off[v], e = g_off[v + 1];
    float mx = -1e30f;
    for (int i = s + lane; i < e; i += 32)
        mx = fmaxf(mx, g_logit[i]);
    for (int o = 16; o; o >>= 1)
        mx = fmaxf(mx, __shfl_xor_sync(0xffffffffu, mx, o));

    float4 accA = make_float4(0.f, 0.f, 0.f, 0.f);
    float4 accB = make_float4(0.f, 0.f, 0.f, 0.f);
    float denA = 0.f, denB = 0.f;
    const __half* hb = g_h_e16 + (size_t)lane * 4;
    int i = s;
    for (; i + 8 <= e; i += 8) {
        float l[8]; uint2 rw[8];
#pragma unroll
        for (int j = 0; j < 8; j++) l[j] = g_logit[i + j];
#pragma unroll
        for (int j = 0; j < 8; j++) rw[j] = *(const uint2*)(hb + (size_t)(i + j) * 128);
        float w[8];
#pragma unroll
        for (int j = 0; j < 8; j++) w[j] = __expf(l[j] - mx);
#pragma unroll
        for (int j = 0; j < 8; j++) {
            float2 a = __half22float2(*(__half2*)&rw[j].x);
            float2 b = __half22float2(*(__half2*)&rw[j].y);
            if (j & 1) {
                denB += w[j];
                accB.x += w[j] * a.x; accB.y += w[j] * a.y;
                accB.z += w[j] * b.x; accB.w += w[j] * b.y;
            } else {
                denA += w[j];
                accA.x += w[j] * a.x; accA.y += w[j] * a.y;
                accA.z += w[j] * b.x; accA.w += w[j] * b.y;
            }
        }
    }
    for (; i < e; i++) {
        float w = __expf(g_logit[i] - mx);
        uint2 raw = *(const uint2*)(hb + (size_t)i * 128);
        float2 f01 = __half22float2(*(__half2*)&raw.x);
        float2 f23 = __half22float2(*(__half2*)&raw.y);
        denA += w;
        accA.x += w * f01.x; accA.y += w * f01.y;
        accA.z += w * f23.x; accA.w += w * f23.y;
    }
    float den = denA + denB;
    float inv = (e > s) ? 1.f / den : 0.f;
    __half2 p01 = __floats2half2_rn((accA.x + accB.x) * inv, (accA.y + accB.y) * inv);
    __half2 p23 = __floats2half2_rn((accA.z + accB.z) * inv, (accA.w + accB.w) * inv);
    *(uint2*)&g_A16[v * 128 + lane * 4] = make_uint2(*(uint32_t*)&p01, *(uint32_t*)&p23);
}

// ============ shared HMMA helpers (M=64 x N=32 warp tile, B-dedup) ============
__device__ __forceinline__ void gemm_acc_m64n32(
    uint32_t Ab, uint32_t aOffL, const uint4* __restrict__ bf, int qb, float acc[4][4][4])
{
#pragma unroll
    for (int k8 = 0; k8 < 8; k8++) {
        uint32_t kb = k8 * 32;
        uint4 b0 = bf[k8 * 128 + (qb + 0) * 32];
        uint4 b1 = bf[k8 * 128 + (qb + 1) * 32];
        uint32_t a[4][4];
#pragma unroll
        for (int ms = 0; ms < 4; ms++)
            ldsm_x4(a[ms], Ab + aOffL + (uint32_t)(ms * 16) * 272 + kb);
        const uint32_t* p0 = (const uint32_t*)&b0;
        const uint32_t* p1 = (const uint32_t*)&b1;
#pragma unroll
        for (int ms = 0; ms < 4; ms++) {
            mma_f16(acc[ms][0], a[ms], p0);
            mma_f16(acc[ms][1], a[ms], p0 + 2);
            mma_f16(acc[ms][2], a[ms], p1);
            mma_f16(acc[ms][3], a[ms], p1 + 2);
        }
    }
}
__device__ __forceinline__ void load_x_tile(char* dstBase, const __half* __restrict__ X,
                                            int e0, int t) {
    int row = t >> 1, hf = t & 1;
    int gr = e0 + row;
    uint4* xd = (uint4*)(dstBase + row * 272 + hf * 128);
    if (gr < N_NODES) {
        const uint4* xp = (const uint4*)(X + (size_t)gr * 128 + hf * 64);
#pragma unroll
        for (int j = 0; j < 8; j++) xd[j] = xp[j];
    } else {
#pragma unroll
        for (int j = 0; j < 8; j++) xd[j] = make_uint4(0, 0, 0, 0);
    }
}

// ============ launch #6: C_v = elu(A @ W_msg + b_msg), HMMA fp16 out ============
#define SM16_BIAS 0
#define SM16_X    512
#define SM16_TOTAL (SM16_X + 64 * 272)   // 17920 bytes

__global__ __launch_bounds__(128, 4) void cv16_kernel(const float* __restrict__ b_msg) {
    extern __shared__ __align__(16) char smem[];
    uint32_t sb = smem_u32(smem);
    int t = threadIdx.x, lane = t & 31, wid = t >> 5;
    int e0 = blockIdx.x * 64;
    float* sBias = (float*)(smem + SM16_BIAS);
    sBias[t] = b_msg[t];
    load_x_tile(smem + SM16_X, g_A16, e0, t);
    __syncthreads();

    int s = wid, n0 = s * 32;
    float acc[4][4][4];
#pragma unroll
    for (int i = 0; i < 4; i++)
#pragma unroll
        for (int j = 0; j < 4; j++)
#pragma unroll
            for (int c = 0; c < 4; c++) acc[i][j][c] = 0.f;
    uint32_t aOffL = ((lane & 15) * A_STRIDE + (lane >> 4) * 8) * 2;
    gemm_acc_m64n32(sb + SM16_X, aOffL, g_WmsgFrag + (s >> 1) * 1024 + lane, (s & 1) * 2, acc);

#pragma unroll
    for (int ms = 0; ms < 4; ms++) {
        int r1 = ms * 16 + (lane >> 2);
#pragma unroll
        for (int rr = 0; rr < 2; rr++) {
            int gr = e0 + r1 + rr * 8;
            if (gr >= N_NODES) continue;
#pragma unroll
            for (int ns = 0; ns < 4; ns++) {
                int col = n0 + ns * 8 + (lane & 3) * 2;
                float v0 = acc[ms][ns][rr * 2]     + sBias[col];
                float v1 = acc[ms][ns][rr * 2 + 1] + sBias[col + 1];
                v0 = (v0 > 0.f) ? v0 : (__expf(v0) - 1.f);
                v1 = (v1 > 0.f) ? v1 : (__expf(v1) - 1.f);
                *(__half2*)(g_cv16 + (size_t)gr * 128 + col) = __floats2half2_rn(v0, v1);
            }
        }
    }
}

// ============ launch #7: GRU pre-gates, 4 modes ============
// mode 0: gr = cv@Wih_r + hv@Whh_r + b_ih_r + b_hh_r   -> g_gi[0..]
// mode 1: gz (chunk 1)                                  -> g_gi[N*128..]
// mode 2: gin = cv@Wih_n + b_ih_n                       -> g_gi[2*N*128..]
// mode 3: ghn = hv@Whh_n + b_hh_n                       -> g_gh
#define SMG_BIAS 0
#define SMG_X1   512
#define SMG_X2   (SMG_X1 + 17408)
#define SMG_TOTAL (SMG_X2 + 17408)   // 35328 bytes

__global__ __launch_bounds__(128) void gru16_kernel(const float* __restrict__ b_ih,
                                                    const float* __restrict__ b_hh) {
    extern __shared__ __align__(16) char smem[];
    uint32_t sb = smem_u32(smem);
    int t = threadIdx.x, lane = t & 31, wid = t >> 5;
    int mode = blockIdx.y;
    int e0 = blockIdx.x * 64;
    float* sBias = (float*)(smem + SMG_BIAS);
    if (mode == 0)      sBias[t] = b_ih[t] + b_hh[t];
    else if (mode == 1) sBias[t] = b_ih[128 + t] + b_hh[128 + t];
    else if (mode == 2) sBias[t] = b_ih[256 + t];
    else                sBias[t] = b_hh[256 + t];

    const __half* X1 = (mode == 3) ? g_h_v16 : g_cv16;
    load_x_tile(smem + SMG_X1, X1, e0, t);
    if (mode < 2) load_x_tile(smem + SMG_X2, g_h_v16, e0, t);
    __syncthreads();

    int s = wid, n0 = s * 32;
    float acc[4][4][4];
#pragma unroll
    for (int i = 0; i < 4; i++)
#pragma unroll
        for (int j = 0; j < 4; j++)
#pragma unroll
            for (int c = 0; c < 4; c++) acc[i][j][c] = 0.f;
    uint32_t aOffL = ((lane & 15) * A_STRIDE + (lane >> 4) * 8) * 2;
    int foff = (s >> 1) * 1024 + lane;
    int qb = (s & 1) * 2;

    int chunk = (mode < 2) ? mode : 2;
    const uint4* bf1 = ((mode == 3) ? g_WhhFrag : g_WihFrag) + chunk * 2048 + foff;
    gemm_acc_m64n32(sb + SMG_X1, aOffL, bf1, qb, acc);
    if (mode < 2)
        gemm_acc_m64n32(sb + SMG_X2, aOffL, g_WhhFrag + chunk * 2048 + foff, qb, acc);

    float* outp = (mode == 3) ? g_gh : (g_gi + (size_t)mode * N_NODES * 128);
#pragma unroll
    for (int ms = 0; ms < 4; ms++) {
        int r1 = ms * 16 + (lane >> 2);
#pragma unroll
        for (int rr = 0; rr < 2; rr++) {
            int gr = e0 + r1 + rr * 8;
            if (gr >= N_NODES) continue;
#pragma unroll
            for (int ns = 0; ns < 4; ns++) {
                int col = n0 + ns * 8 + (lane & 3) * 2;
                *(float2*)(outp + (size_t)gr * 128 + col) = make_float2(
                    acc[ms][ns][rr * 2] + sBias[col],
                    acc[ms][ns][rr * 2 + 1] + sBias[col + 1]);
            }
        }
    }
}

// ---------------- launch #8: GRU gates + relu (flat, coalesced) ----------------
__global__ void gate_kernel(float* __restrict__ out) {
    int idx = blockIdx.x * blockDim.x + threadIdx.x;
    if (idx >= N_NODES * NHID) return;
    float r = 1.f / (1.f + __expf(-g_gi[idx]));
    float z = 1.f / (1.f + __expf(-g_gi[N_NODES * 128 + idx]));
    float nn = tanhf(g_gi[2 * N_NODES * 128 + idx] + r * g_gh[idx]);
    float hv = g_h_v[idx];
    float h = (1.f - z) * nn + z * hv;
    out[idx] = h > 0.f ? h : 0.f;
}

// ---------------- launch ----------------
extern "C" void kernel_launch(void* const* d_in, const int* in_sizes, int n_in,
                              void* d_out, int out_size) {
    const float* node_feats = (const float*)d_in[0];
    const float* edge_feats = (const float*)d_in[1];
    const float* W_node  = (const float*)d_in[2];
    const float* b_node  = (const float*)d_in[3];
    const float* W_edge  = (const float*)d_in[4];
    const float* b_edge  = (const float*)d_in[5];
    const float* W_logit = (const float*)d_in[6];
    const float* b_logit = (const float*)d_in[7];
    const float* W_msg   = (const float*)d_in[8];
    const float* b_msg   = (const float*)d_in[9];
    const float* W_ih    = (const float*)d_in[10];
    const float* W_hh    = (const float*)d_in[11];
    const float* b_ih    = (const float*)d_in[12];
    const float* b_hh    = (const float*)d_in[13];
    const int*   src     = (const int*)d_in[14];
    const int*   dst     = (const int*)d_in[15];
    float* out = (float*)d_out;

    int* p_cnt;
    __half* p_nf16;
    cudaGetSymbolAddress((void**)&p_cnt, g_cnt);
    cudaGetSymbolAddress((void**)&p_nf16, g_nf16);

    const int SM_NODE = (64 * 128 + 64 * 64 + 256) * 4;
    cudaFuncSetAttribute(edge_mma_kernel, cudaFuncAttributeMaxDynamicSharedMemorySize, SM_EDGE_TOTAL);
    cudaFuncSetAttribute(node_embed_kernel, cudaFuncAttributeMaxDynamicSharedMemorySize, SM_NODE);
    cudaFuncSetAttribute(cv16_kernel, cudaFuncAttributeMaxDynamicSharedMemorySize, SM16_TOTAL);
    cudaFuncSetAttribute(gru16_kernel, cudaFuncAttributeMaxDynamicSharedMemorySize, SMG_TOTAL);

    cudaMemsetAsync(p_cnt, 0, N_NODES * sizeof(int));

    // #1 histogram + nf16 + all fragment prep
    hist_prep_kernel<<<(N_EDGES + 255) / 256, 256>>>(dst, node_feats, W_edge, W_ih, W_hh, W_msg);
    // #2 scan (warp-shuffle)
    scan_kernel<<<1, 1024>>>();
    // #3 node embed + fused hvdot + fp16 copy
    int ntiles64 = (N_NODES + 63) / 64;
    node_embed_kernel<<<ntiles64, 256, SM_NODE>>>(node_feats, W_node, b_node, W_logit);
    // #4 edge GEMM on tensor cores (profiled slot)
    float* outEF = (out_size >= N_NODES * NHID + N_EDGES * 64) ? (out + N_NODES * NHID) : nullptr;
    edge_mma_kernel<<<N_EDGES / 64, 128, SM_EDGE_TOTAL>>>(p_nf16, edge_feats, src, dst,
                                                          b_edge, W_logit, b_logit, outEF);
    // #5 softmax-weighted segment sum -> A16 (8x unrolled)
    aggregate_kernel<<<(N_NODES + 7) / 8, 256>>>();
    // #6 C_v (HMMA, fp16 out)
    cv16_kernel<<<ntiles64, 128, SM16_TOTAL>>>(b_msg);
    // #7 GRU pre-gates: 4 modes (r_sum, z_sum, gi_n, gh_n)
    gru16_kernel<<<dim3(ntiles64, 4), 128, SMG_TOTAL>>>(b_ih, b_hh);
    // #8 gates -> h_new
    gate_kernel<<<(N_NODES * NHID + 255) / 256, 256>>>(out);
}